// round 10
// baseline (speedup 1.0000x reference)
#include <cuda_runtime.h>
#include <cuda_bf16.h>

// y[b,c,h,w] = coef[c] * g[b,c,h,w]
// g: (32, 512, 64, 64) fp32, coef: (512,) fp32.
//
// Best-measured operating point (R4): one block = 256 threads x 4 float4 =
// one 4096-float (b,c) channel plane; grid = 16384; block-uniform coef
// (c = blockIdx.x & 511); 4 front-batched LDG.128.cs (MLP=4/thread);
// .cs evict-first on the zero-reuse 512 MiB stream.
//
// This round's delta: stores issued immediately after each multiply
// (instead of all-loads -> all-FMULs -> all-stores). Load MLP unchanged
// (all 4 loads are issued before the first store's operand is ready);
// stores enter the LSU ~1 load-latency earlier, smoothing the chip-wide
// DRAM read/write interleave.

__global__ __launch_bounds__(256)
void Gradient_28733331210651_kernel(const float4* __restrict__ g4,
                                    const float* __restrict__ coef,
                                    float4* __restrict__ out4) {
    const int c = blockIdx.x & 511;
    const float s = __ldg(coef + c);

    const long long base = (long long)blockIdx.x * 1024 + threadIdx.x;

    // Front-batched loads (MLP=4)
    float4 v0 = __ldcs(g4 + base);
    float4 v1 = __ldcs(g4 + base + 256);
    float4 v2 = __ldcs(g4 + base + 512);
    float4 v3 = __ldcs(g4 + base + 768);

    // Scale + store each tile as soon as it's ready
    v0.x *= s; v0.y *= s; v0.z *= s; v0.w *= s;
    __stcs(out4 + base,       v0);
    v1.x *= s; v1.y *= s; v1.z *= s; v1.w *= s;
    __stcs(out4 + base + 256, v1);
    v2.x *= s; v2.y *= s; v2.z *= s; v2.w *= s;
    __stcs(out4 + base + 512, v2);
    v3.x *= s; v3.y *= s; v3.z *= s; v3.w *= s;
    __stcs(out4 + base + 768, v3);
}

extern "C" void kernel_launch(void* const* d_in, const int* in_sizes, int n_in,
                              void* d_out, int out_size) {
    const float4* g4   = (const float4*)d_in[0];
    const float*  coef = (const float*)d_in[1];
    float4*       out4 = (float4*)d_out;

    // 32*512*64*64 floats; one block per 4096-float channel plane
    long long n  = (long long)in_sizes[0];      // 67108864
    long long blocks = n >> 12;                 // 16384

    Gradient_28733331210651_kernel<<<(unsigned)blocks, 256>>>(g4, coef, out4);
}

// round 11
// speedup vs baseline: 1.0027x; 1.0027x over previous
#include <cuda_runtime.h>
#include <cuda_bf16.h>

// y[b,c,h,w] = coef[c] * g[b,c,h,w]
// g: (32, 512, 64, 64) fp32, coef: (512,) fp32.
//
// FINAL config — best of 7 measured variants (harness 81.95us, ncu 73.3us,
// DRAM 83.0% / 6.57 TB/s):
//   - one block = 256 threads x 4 float4 = one 4096-float (b,c) channel
//     plane; grid = 16384; coef index block-uniform (c = blockIdx.x & 511)
//   - ILP=4 front-batched LDG.128 (MLP=4 outstanding loads/thread), then
//     FMULs, then 4 STG.128
//   - .cs (evict-first) on both loads and stores: zero-reuse 512 MiB stream
// Measured ties/regressions ruled out: MLP=8 (reg pressure), 256-bit
// accesses, persistent grid-stride (loop-carried MLP throttle), 512-thread
// blocks, interleaved store scheduling. Sustained harness time is pinned at
// ~6.5 TB/s effective by steady-state clocks; this config sits on that floor.

__global__ __launch_bounds__(256)
void Gradient_28733331210651_kernel(const float4* __restrict__ g4,
                                    const float* __restrict__ coef,
                                    float4* __restrict__ out4) {
    // Block-uniform channel + scale
    const int c = blockIdx.x & 511;
    const float s = __ldg(coef + c);

    const long long base = (long long)blockIdx.x * 1024 + threadIdx.x;

    // Front-batched loads (MLP=4)
    float4 v0 = __ldcs(g4 + base);
    float4 v1 = __ldcs(g4 + base + 256);
    float4 v2 = __ldcs(g4 + base + 512);
    float4 v3 = __ldcs(g4 + base + 768);

    v0.x *= s; v0.y *= s; v0.z *= s; v0.w *= s;
    v1.x *= s; v1.y *= s; v1.z *= s; v1.w *= s;
    v2.x *= s; v2.y *= s; v2.z *= s; v2.w *= s;
    v3.x *= s; v3.y *= s; v3.z *= s; v3.w *= s;

    __stcs(out4 + base,       v0);
    __stcs(out4 + base + 256, v1);
    __stcs(out4 + base + 512, v2);
    __stcs(out4 + base + 768, v3);
}

extern "C" void kernel_launch(void* const* d_in, const int* in_sizes, int n_in,
                              void* d_out, int out_size) {
    const float4* g4   = (const float4*)d_in[0];
    const float*  coef = (const float*)d_in[1];
    float4*       out4 = (float4*)d_out;

    // 32*512*64*64 floats; one block per 4096-float channel plane
    long long n  = (long long)in_sizes[0];      // 67108864
    long long blocks = n >> 12;                 // 16384

    Gradient_28733331210651_kernel<<<(unsigned)blocks, 256>>>(g4, coef, out4);
}